// round 1
// baseline (speedup 1.0000x reference)
#include <cuda_runtime.h>
#include <math.h>

// Problem constants
#define BATCH   2
#define LSEQ    4096
#define DIMSZ   512
#define NHEADS  8
#define HD      64
#define KSZ     33
#define MROWS   (BATCH * LSEQ)        // 8192
#define QKVDIM  (3 * DIMSZ)           // 1536
#define BQ      128                   // queries per attention block
#define PITCH   161                   // smem pitch for K/V tiles (odd -> conflict free)
#define NKMAX   160

// Scratch (device globals: no allocation allowed)
__device__ float g_qkv[(size_t)MROWS * QKVDIM];   // ~50.3 MB
__device__ float g_att[(size_t)MROWS * DIMSZ];    // ~16.8 MB

// ----------------------------------------------------------------------------
// GEMM (NT): C[M,N] = A[M,K] @ B[N,K]^T + bias[N]
// BM=BN=128, BK=16, 256 threads, 8x8 per-thread micro-tile. M,N,K divisible.
// ----------------------------------------------------------------------------
__global__ void __launch_bounds__(256) gemm_nt_bias(
    const float* __restrict__ A, const float* __restrict__ B,
    const float* __restrict__ bias, float* __restrict__ C,
    int N, int K)
{
    __shared__ float As[16][128];
    __shared__ float Bs[16][128];

    const int tid = threadIdx.x;
    const int m0 = blockIdx.y * 128;
    const int n0 = blockIdx.x * 128;
    const int tm = tid >> 4;    // 0..15
    const int tn = tid & 15;    // 0..15

    float acc[8][8];
#pragma unroll
    for (int i = 0; i < 8; i++)
#pragma unroll
        for (int j = 0; j < 8; j++) acc[i][j] = 0.0f;

    const float* Ag = A + (size_t)m0 * K;
    const float* Bg = B + (size_t)n0 * K;

    for (int k0 = 0; k0 < K; k0 += 16) {
        // Stage tiles: 128 rows x 16 k each = 512 float4 per operand
#pragma unroll
        for (int u = 0; u < 2; u++) {
            int i4  = tid + u * 256;   // 0..511
            int row = i4 >> 2;
            int c4  = i4 & 3;
            float4 av = *(const float4*)(Ag + (size_t)row * K + k0 + c4 * 4);
            As[c4 * 4 + 0][row] = av.x;
            As[c4 * 4 + 1][row] = av.y;
            As[c4 * 4 + 2][row] = av.z;
            As[c4 * 4 + 3][row] = av.w;
            float4 bv = *(const float4*)(Bg + (size_t)row * K + k0 + c4 * 4);
            Bs[c4 * 4 + 0][row] = bv.x;
            Bs[c4 * 4 + 1][row] = bv.y;
            Bs[c4 * 4 + 2][row] = bv.z;
            Bs[c4 * 4 + 3][row] = bv.w;
        }
        __syncthreads();

#pragma unroll
        for (int kk = 0; kk < 16; kk++) {
            float a[8], b[8];
            *(float4*)&a[0] = *(const float4*)&As[kk][tm * 8];
            *(float4*)&a[4] = *(const float4*)&As[kk][tm * 8 + 4];
            *(float4*)&b[0] = *(const float4*)&Bs[kk][tn * 8];
            *(float4*)&b[4] = *(const float4*)&Bs[kk][tn * 8 + 4];
#pragma unroll
            for (int i = 0; i < 8; i++)
#pragma unroll
                for (int j = 0; j < 8; j++)
                    acc[i][j] = fmaf(a[i], b[j], acc[i][j]);
        }
        __syncthreads();
    }

    // Epilogue: bias + store
    float bv[8];
#pragma unroll
    for (int j = 0; j < 8; j++) bv[j] = bias[n0 + tn * 8 + j];

#pragma unroll
    for (int i = 0; i < 8; i++) {
        float4 o0, o1;
        o0.x = acc[i][0] + bv[0];
        o0.y = acc[i][1] + bv[1];
        o0.z = acc[i][2] + bv[2];
        o0.w = acc[i][3] + bv[3];
        o1.x = acc[i][4] + bv[4];
        o1.y = acc[i][5] + bv[5];
        o1.z = acc[i][6] + bv[6];
        o1.w = acc[i][7] + bv[7];
        float* cp = C + (size_t)(m0 + tm * 8 + i) * N + n0 + tn * 8;
        *(float4*)(cp)     = o0;
        *(float4*)(cp + 4) = o1;
    }
}

// ----------------------------------------------------------------------------
// Neighborhood attention. One block per (b, h, 128-query tile).
// K/V windows of the tile (<=160 keys) staged d-major in smem; 1 thread/query.
// ----------------------------------------------------------------------------
__global__ void __launch_bounds__(128) na1d_kernel(
    const float* __restrict__ qkv, float* __restrict__ outp)
{
    extern __shared__ float sh[];
    float* Ks = sh;                       // [64][PITCH]
    float* Vs = sh + 64 * PITCH;          // [64][PITCH]
    float* Sc = sh + 2 * 64 * PITCH;      // [KSZ][128]

    const int b  = blockIdx.z;
    const int h  = blockIdx.y;
    const int q0 = blockIdx.x * BQ;

    const int smin = min(max(q0 - (KSZ / 2), 0), LSEQ - KSZ);
    const int smax = min(max(q0 + BQ - 1 - (KSZ / 2), 0), LSEQ - KSZ);
    const int nk   = smax - smin + KSZ;   // <= 160

    // Stage K and V windows: Ks[d][j] = K[b, smin+j, h, d]
    const float* kb = qkv + ((size_t)(b * LSEQ + smin)) * QKVDIM + DIMSZ + h * HD;
    for (int idx = threadIdx.x; idx < nk * HD; idx += 128) {
        int j = idx >> 6;
        int d = idx & 63;
        float kv = kb[(size_t)j * QKVDIM + d];
        float vv = kb[(size_t)j * QKVDIM + DIMSZ + d];
        Ks[d * PITCH + j] = kv;
        Vs[d * PITCH + j] = vv;
    }
    __syncthreads();

    const int l   = q0 + threadIdx.x;
    const int st  = min(max(l - (KSZ / 2), 0), LSEQ - KSZ);
    const int ks0 = st - smin;

    const float* qp = qkv + ((size_t)(b * LSEQ + l)) * QKVDIM + h * HD;
    float q[HD];
#pragma unroll
    for (int d = 0; d < HD; d++) q[d] = qp[d] * 0.125f;  // SCALE = 64^-0.5

    // Scores
    float mx = -1e30f;
    for (int j = 0; j < KSZ; j++) {
        const float* kcol = Ks + ks0 + j;
        float s = 0.0f;
#pragma unroll
        for (int d = 0; d < HD; d++) s = fmaf(q[d], kcol[d * PITCH], s);
        Sc[j * 128 + threadIdx.x] = s;
        mx = fmaxf(mx, s);
    }

    // Softmax weights
    float sum = 0.0f;
    for (int j = 0; j < KSZ; j++) {
        float p = __expf(Sc[j * 128 + threadIdx.x] - mx);
        Sc[j * 128 + threadIdx.x] = p;
        sum += p;
    }
    const float inv = 1.0f / sum;

    // Weighted V accumulation
    float o[HD];
#pragma unroll
    for (int d = 0; d < HD; d++) o[d] = 0.0f;
    for (int j = 0; j < KSZ; j++) {
        float p = Sc[j * 128 + threadIdx.x];
        const float* vcol = Vs + ks0 + j;
#pragma unroll
        for (int d = 0; d < HD; d++) o[d] = fmaf(p, vcol[d * PITCH], o[d]);
    }

    float* op = outp + ((size_t)(b * LSEQ + l)) * DIMSZ + h * HD;
#pragma unroll
    for (int d = 0; d < HD; d++) op[d] = o[d] * inv;
}

// ----------------------------------------------------------------------------
// Launch
// ----------------------------------------------------------------------------
extern "C" void kernel_launch(void* const* d_in, const int* in_sizes, int n_in,
                              void* d_out, int out_size)
{
    const float* x      = (const float*)d_in[0];
    const float* w_qkv  = (const float*)d_in[1];
    const float* b_qkv  = (const float*)d_in[2];
    const float* w_proj = (const float*)d_in[3];
    const float* b_proj = (const float*)d_in[4];
    float*       out    = (float*)d_out;

    float* qkv = nullptr;
    float* att = nullptr;
    cudaGetSymbolAddress((void**)&qkv, g_qkv);
    cudaGetSymbolAddress((void**)&att, g_att);

    const int att_smem = (2 * 64 * PITCH + KSZ * 128) * sizeof(float);  // 99328 B
    cudaFuncSetAttribute(na1d_kernel,
                         cudaFuncAttributeMaxDynamicSharedMemorySize, att_smem);

    // 1) QKV projection: [8192,512] @ [1536,512]^T + b -> [8192,1536]
    dim3 g1(QKVDIM / 128, MROWS / 128);
    gemm_nt_bias<<<g1, 256>>>(x, w_qkv, b_qkv, qkv, QKVDIM, DIMSZ);

    // 2) Neighborhood attention -> [8192,512]
    dim3 g2(LSEQ / BQ, NHEADS, BATCH);
    na1d_kernel<<<g2, 128, att_smem>>>(qkv, att);

    // 3) Output projection: [8192,512] @ [512,512]^T + b -> d_out
    dim3 g3(DIMSZ / 128, MROWS / 128);
    gemm_nt_bias<<<g3, 256>>>(att, w_proj, b_proj, out, DIMSZ, DIMSZ);
}